// round 2
// baseline (speedup 1.0000x reference)
#include <cuda_runtime.h>

#define NE      20000
#define KMAX    16
#define NTRIP   (NE * KMAX)
#define EMB     128
#define INTERM  64
#define NSPH    7
#define NOUT    128
#define MT      32          // edges per CTA
#define NTHREADS 256

typedef unsigned long long ull;

// persistent scratch: triplet gather index (pos = edge*16 + slot -> triplet id)
__device__ int d_trip[NE * KMAX];
__device__ int d_is64;

__device__ __forceinline__ ull pack2(float x, float y) {
    ull r; asm("mov.b64 %0, {%1,%2};" : "=l"(r) : "f"(x), "f"(y)); return r;
}
__device__ __forceinline__ void unpack2(ull v, float& x, float& y) {
    asm("mov.b64 {%0,%1}, %2;" : "=f"(x), "=f"(y) : "l"(v));
}
__device__ __forceinline__ ull ffma2(ull a, ull b, ull c) {
    ull d; asm("fma.rn.f32x2 %0, %1, %2, %3;" : "=l"(d) : "l"(a), "l"(b), "l"(c)); return d;
}

// Decide whether index buffers are int64 or int32.
// int32 data viewed as int64 fuses adjacent values -> out of range quickly.
__global__ void detect_kernel(const void* idr, const void* kix, int n) {
    __shared__ int bad;
    if (threadIdx.x == 0) bad = 0;
    __syncthreads();
    int cnt = n < 2048 ? n : 2048;
    const long long* a = (const long long*)idr;
    const long long* b = (const long long*)kix;
    for (int t = threadIdx.x; t < cnt; t += blockDim.x) {
        long long v = a[t], w = b[t];
        if (v < 0 || v >= NE || w < 0 || w >= KMAX) bad = 1;
    }
    __syncthreads();
    if (threadIdx.x == 0) d_is64 = bad ? 0 : 1;
}

__global__ void build_idx_kernel(const void* idr, const void* kix, int n) {
    int t = blockIdx.x * blockDim.x + threadIdx.x;
    if (t >= n) return;
    int e, k;
    if (d_is64) {
        e = (int)((const long long*)idr)[t];
        k = (int)((const long long*)kix)[t];
    } else {
        e = ((const int*)idr)[t];
        k = ((const int*)kix)[t];
    }
    if (e >= 0 && e < NE && k >= 0 && k < KMAX)
        d_trip[e * KMAX + k] = t;
}

// ---- shared memory layout (float offsets) ----
#define OFF_SUMK 0
#define SZ_SUMK  (MT * 128 * 8)          // [n][e][8]  (7 used + 1 pad)
#define OFF_W    (OFF_SUMK + SZ_SUMK)
#define SZ_W     (2 * INTERM * EMB)      // double-buffered weight[e] slice
#define OFF_A    (OFF_W + SZ_W)
#define SZ_A     (MT * 65)               // [n][i] pitch 65
#define OFF_SPH  (OFF_A + SZ_A)
#define SZ_SPH   (MT * NSPH * KMAX)
#define OFF_TRIP (OFF_SPH + SZ_SPH)
#define SZ_TRIP  (MT * KMAX)             // ints
#define SMEM_FLOATS (OFF_TRIP + SZ_TRIP)
#define SMEM_BYTES  (SMEM_FLOATS * 4)    // = 221312 B

__global__ __launch_bounds__(NTHREADS, 1)
void fused_bilinear_kernel(const float* __restrict__ rbf,
                           const float* __restrict__ sph,
                           const float* __restrict__ m,
                           const float* __restrict__ weight,
                           float* __restrict__ out) {
    extern __shared__ float sm[];
    float* s_sumk = sm + OFF_SUMK;
    float* s_W    = sm + OFF_W;
    float* s_A    = sm + OFF_A;
    float* s_sph  = sm + OFF_SPH;
    int*   s_trip = (int*)(sm + OFF_TRIP);

    const int tid  = threadIdx.x;
    const int warp = tid >> 5, lane = tid & 31;
    const int n0   = blockIdx.x * MT;

    // stage sph tile + gather indices
    for (int x = tid; x < MT * NSPH * KMAX; x += NTHREADS)
        s_sph[x] = sph[(size_t)n0 * (NSPH * KMAX) + x];
    for (int x = tid; x < MT * KMAX; x += NTHREADS) {
        int tr = d_trip[n0 * KMAX + x];
        // clamp so no downstream index path can go out of bounds
        s_trip[x] = (tr < 0) ? 0 : (tr >= NTRIP ? NTRIP - 1 : tr);
    }

    // rbf_W1 tile held in registers: p -> (n = warp + 8*(p&3), i = lane + 32*(p>>2))
    float rr[8][7];
    #pragma unroll
    for (int p = 0; p < 8; ++p) {
        int n = warp + 8 * (p & 3);
        int i = lane + 32 * (p >> 2);
        const float* rp = rbf + ((size_t)(n0 + n) * INTERM + i) * NSPH;
        #pragma unroll
        for (int s = 0; s < 7; ++s) rr[p][s] = rp[s];
    }

    __syncthreads();

    // ---- phase 1: sum_k[n][e][s] = sum_k sph[n][s][k] * m[trip(n,k)][e] ----
    #pragma unroll
    for (int t = 0; t < 4; ++t) {
        int n  = warp + 8 * t;
        int tb = n * KMAX;
        const float* sp = s_sph + n * (NSPH * KMAX);
        #pragma unroll
        for (int q = 0; q < 4; ++q) {
            int e = lane + 32 * q;
            float mc[16];
            #pragma unroll
            for (int k = 0; k < 16; ++k)
                mc[k] = m[(size_t)s_trip[tb + k] * EMB + e];
            float* dst = s_sumk + n * 1024 + e * 8;
            #pragma unroll
            for (int s = 0; s < 7; ++s) {
                float acc = 0.f;
                #pragma unroll
                for (int k = 0; k < 16; ++k) acc += sp[s * 16 + k] * mc[k];
                dst[s] = acc;
            }
        }
    }

    // preload weight[e=0] slice (64x128 = 32KB) into buffer 0
    {
        const float4* wg = (const float4*)weight;
        float4* ws = (float4*)s_W;
        #pragma unroll
        for (int j = 0; j < 8; ++j) ws[tid + 256 * j] = wg[tid + 256 * j];
    }
    __syncthreads();

    // ---- phases 2+3, looped over e ----
    const int ng = tid >> 4, og = tid & 15;
    const int nb = ng * 2,   ob = og * 8;

    ull c[2][4];
    #pragma unroll
    for (int a = 0; a < 2; ++a)
        #pragma unroll
        for (int b = 0; b < 4; ++b) c[a][b] = 0ULL;

    int buf = 0;
    for (int e = 0; e < EMB; ++e) {
        // prefetch weight[e+1] into registers (hidden under GEMM)
        float4 wp[8];
        if (e + 1 < EMB) {
            const float4* wg = (const float4*)(weight + (size_t)(e + 1) * INTERM * EMB);
            #pragma unroll
            for (int j = 0; j < 8; ++j) wp[j] = wg[tid + 256 * j];
        }

        // phase 2: A_e[n][i] = sum_s rbf[n][i][s] * sum_k[n][s][e]
        #pragma unroll
        for (int p = 0; p < 8; ++p) {
            int n = warp + 8 * (p & 3);
            int i = lane + 32 * (p >> 2);
            const float* sk = s_sumk + n * 1024 + e * 8;
            float4 v0 = *(const float4*)sk;
            float4 v1 = *(const float4*)(sk + 4);
            float a = rr[p][0] * v0.x + rr[p][1] * v0.y + rr[p][2] * v0.z + rr[p][3] * v0.w
                    + rr[p][4] * v1.x + rr[p][5] * v1.y + rr[p][6] * v1.z;
            s_A[n * 65 + i] = a;
        }
        __syncthreads();

        // phase 3: C[n][o] += A_e[n][i] * W_e[i][o]   (FFMA2 over o-pairs)
        const float* wrow  = s_W + buf * (INTERM * EMB);
        const float* arow0 = s_A + nb * 65;
        const float* arow1 = s_A + (nb + 1) * 65;
        #pragma unroll 16
        for (int i = 0; i < INTERM; ++i) {
            ulonglong2 wA = *(const ulonglong2*)(wrow + i * EMB + ob);
            ulonglong2 wB = *(const ulonglong2*)(wrow + i * EMB + ob + 4);
            float af0 = arow0[i], af1 = arow1[i];
            ull a0 = pack2(af0, af0);
            ull a1 = pack2(af1, af1);
            c[0][0] = ffma2(a0, wA.x, c[0][0]);
            c[0][1] = ffma2(a0, wA.y, c[0][1]);
            c[0][2] = ffma2(a0, wB.x, c[0][2]);
            c[0][3] = ffma2(a0, wB.y, c[0][3]);
            c[1][0] = ffma2(a1, wA.x, c[1][0]);
            c[1][1] = ffma2(a1, wA.y, c[1][1]);
            c[1][2] = ffma2(a1, wB.x, c[1][2]);
            c[1][3] = ffma2(a1, wB.y, c[1][3]);
        }

        // commit prefetched weight slice to the other buffer
        if (e + 1 < EMB) {
            float4* ws = (float4*)(s_W + (buf ^ 1) * (INTERM * EMB));
            #pragma unroll
            for (int j = 0; j < 8; ++j) ws[tid + 256 * j] = wp[j];
        }
        __syncthreads();
        buf ^= 1;
    }

    // write C tile: thread owns edges (nb, nb+1), outputs [ob, ob+8)
    #pragma unroll
    for (int nn = 0; nn < 2; ++nn) {
        float o8[8];
        #pragma unroll
        for (int j = 0; j < 4; ++j) unpack2(c[nn][j], o8[2 * j], o8[2 * j + 1]);
        float4* dst = (float4*)(out + (size_t)(n0 + nb + nn) * NOUT + ob);
        dst[0] = make_float4(o8[0], o8[1], o8[2], o8[3]);
        dst[1] = make_float4(o8[4], o8[5], o8[6], o8[7]);
    }
}

extern "C" void kernel_launch(void* const* d_in, const int* in_sizes, int n_in,
                              void* d_out, int out_size) {
    // Remap float inputs by element count (insurance against ordering surprises).
    const float *rbf = 0, *sph = 0, *m = 0, *weight = 0;
    const void *idr = 0, *kix = 0;
    for (int i = 0; i < n_in; ++i) {
        long long sz = in_sizes[i];
        if      (sz == (long long)NE * INTERM * NSPH) rbf = (const float*)d_in[i];
        else if (sz == (long long)NE * NSPH * KMAX)   sph = (const float*)d_in[i];
        else if (sz == (long long)NTRIP * EMB)        m = (const float*)d_in[i];
        else if (sz == (long long)EMB * INTERM * NOUT) weight = (const float*)d_in[i];
        else if (sz == (long long)NTRIP) { if (!idr) idr = d_in[i]; else kix = d_in[i]; }
    }
    float* out = (float*)d_out;

    cudaFuncSetAttribute(fused_bilinear_kernel,
                         cudaFuncAttributeMaxDynamicSharedMemorySize, SMEM_BYTES);

    detect_kernel<<<1, 256>>>(idr, kix, NTRIP);
    build_idx_kernel<<<(NTRIP + 255) / 256, 256>>>(idr, kix, NTRIP);
    fused_bilinear_kernel<<<NE / MT, NTHREADS, SMEM_BYTES>>>(rbf, sph, m, weight, out);
}

// round 3
// speedup vs baseline: 1.0004x; 1.0004x over previous
#include <cuda_runtime.h>

#define NE      20000
#define KMAX    16
#define NTRIP   (NE * KMAX)
#define EMB     128
#define INTERM  64
#define NSPH    7
#define NOUT    128
#define MT      32          // edges per CTA
#define NTHREADS 256

typedef unsigned long long ull;

// persistent scratch: triplet gather index (pos = edge*16 + slot -> triplet id)
__device__ int d_trip[NE * KMAX];
__device__ int d_is64;

__device__ __forceinline__ ull pack2(float x, float y) {
    ull r; asm("mov.b64 %0, {%1,%2};" : "=l"(r) : "f"(x), "f"(y)); return r;
}
__device__ __forceinline__ void unpack2(ull v, float& x, float& y) {
    asm("mov.b64 {%0,%1}, %2;" : "=f"(x), "=f"(y) : "l"(v));
}
__device__ __forceinline__ ull ffma2(ull a, ull b, ull c) {
    ull d; asm("fma.rn.f32x2 %0, %1, %2, %3;" : "=l"(d) : "l"(a), "l"(b), "l"(c)); return d;
}

// Decide whether index buffers are int64 or int32.
// int32 data viewed as int64 fuses adjacent values -> out of range quickly.
__global__ void detect_kernel(const void* idr, const void* kix, int n) {
    __shared__ int bad;
    if (threadIdx.x == 0) bad = 0;
    __syncthreads();
    int cnt = n < 2048 ? n : 2048;
    const long long* a = (const long long*)idr;
    const long long* b = (const long long*)kix;
    for (int t = threadIdx.x; t < cnt; t += blockDim.x) {
        long long v = a[t], w = b[t];
        if (v < 0 || v >= NE || w < 0 || w >= KMAX) bad = 1;
    }
    __syncthreads();
    if (threadIdx.x == 0) d_is64 = bad ? 0 : 1;
}

__global__ void build_idx_kernel(const void* idr, const void* kix, int n) {
    int t = blockIdx.x * blockDim.x + threadIdx.x;
    if (t >= n) return;
    int e, k;
    if (d_is64) {
        e = (int)((const long long*)idr)[t];
        k = (int)((const long long*)kix)[t];
    } else {
        e = ((const int*)idr)[t];
        k = ((const int*)kix)[t];
    }
    if (e >= 0 && e < NE && k >= 0 && k < KMAX)
        d_trip[e * KMAX + k] = t;
}

// ---- shared memory layout (float offsets) ----
#define OFF_SUMK 0
#define SZ_SUMK  (MT * 128 * 8)          // [n][e][8]  (7 used + 1 pad)
#define OFF_W    (OFF_SUMK + SZ_SUMK)
#define SZ_W     (2 * INTERM * EMB)      // double-buffered weight[e] slice
#define OFF_A    (OFF_W + SZ_W)
#define SZ_A     (MT * 65)               // [n][i] pitch 65
#define OFF_SPH  (OFF_A + SZ_A)
#define SZ_SPH   (MT * NSPH * KMAX)
#define OFF_TRIP (OFF_SPH + SZ_SPH)
#define SZ_TRIP  (MT * KMAX)             // ints
#define SMEM_FLOATS (OFF_TRIP + SZ_TRIP)
#define SMEM_BYTES  (SMEM_FLOATS * 4)    // = 221312 B

__global__ __launch_bounds__(NTHREADS, 1)
void fused_bilinear_kernel(const float* __restrict__ rbf,
                           const float* __restrict__ sph,
                           const float* __restrict__ m,
                           const float* __restrict__ weight,
                           float* __restrict__ out) {
    extern __shared__ float sm[];
    float* s_sumk = sm + OFF_SUMK;
    float* s_W    = sm + OFF_W;
    float* s_A    = sm + OFF_A;
    float* s_sph  = sm + OFF_SPH;
    int*   s_trip = (int*)(sm + OFF_TRIP);

    const int tid  = threadIdx.x;
    const int warp = tid >> 5, lane = tid & 31;
    const int n0   = blockIdx.x * MT;

    // stage sph tile + gather indices
    for (int x = tid; x < MT * NSPH * KMAX; x += NTHREADS)
        s_sph[x] = sph[(size_t)n0 * (NSPH * KMAX) + x];
    for (int x = tid; x < MT * KMAX; x += NTHREADS) {
        int tr = d_trip[n0 * KMAX + x];
        // clamp so no downstream index path can go out of bounds
        s_trip[x] = (tr < 0) ? 0 : (tr >= NTRIP ? NTRIP - 1 : tr);
    }

    // rbf_W1 tile held in registers: p -> (n = warp + 8*(p&3), i = lane + 32*(p>>2))
    float rr[8][7];
    #pragma unroll
    for (int p = 0; p < 8; ++p) {
        int n = warp + 8 * (p & 3);
        int i = lane + 32 * (p >> 2);
        const float* rp = rbf + ((size_t)(n0 + n) * INTERM + i) * NSPH;
        #pragma unroll
        for (int s = 0; s < 7; ++s) rr[p][s] = rp[s];
    }

    __syncthreads();

    // ---- phase 1: sum_k[n][e][s] = sum_k sph[n][s][k] * m[trip(n,k)][e] ----
    #pragma unroll
    for (int t = 0; t < 4; ++t) {
        int n  = warp + 8 * t;
        int tb = n * KMAX;
        const float* sp = s_sph + n * (NSPH * KMAX);
        #pragma unroll
        for (int q = 0; q < 4; ++q) {
            int e = lane + 32 * q;
            float mc[16];
            #pragma unroll
            for (int k = 0; k < 16; ++k)
                mc[k] = m[(size_t)s_trip[tb + k] * EMB + e];
            float* dst = s_sumk + n * 1024 + e * 8;
            #pragma unroll
            for (int s = 0; s < 7; ++s) {
                float acc = 0.f;
                #pragma unroll
                for (int k = 0; k < 16; ++k) acc += sp[s * 16 + k] * mc[k];
                dst[s] = acc;
            }
        }
    }

    // preload weight[e=0] slice (64x128 = 32KB) into buffer 0
    {
        const float4* wg = (const float4*)weight;
        float4* ws = (float4*)s_W;
        #pragma unroll
        for (int j = 0; j < 8; ++j) ws[tid + 256 * j] = wg[tid + 256 * j];
    }
    __syncthreads();

    // ---- phases 2+3, looped over e ----
    const int ng = tid >> 4, og = tid & 15;
    const int nb = ng * 2,   ob = og * 8;

    ull c[2][4];
    #pragma unroll
    for (int a = 0; a < 2; ++a)
        #pragma unroll
        for (int b = 0; b < 4; ++b) c[a][b] = 0ULL;

    int buf = 0;
    for (int e = 0; e < EMB; ++e) {
        // prefetch weight[e+1] into registers (hidden under GEMM)
        float4 wp[8];
        if (e + 1 < EMB) {
            const float4* wg = (const float4*)(weight + (size_t)(e + 1) * INTERM * EMB);
            #pragma unroll
            for (int j = 0; j < 8; ++j) wp[j] = wg[tid + 256 * j];
        }

        // phase 2: A_e[n][i] = sum_s rbf[n][i][s] * sum_k[n][s][e]
        #pragma unroll
        for (int p = 0; p < 8; ++p) {
            int n = warp + 8 * (p & 3);
            int i = lane + 32 * (p >> 2);
            const float* sk = s_sumk + n * 1024 + e * 8;
            float4 v0 = *(const float4*)sk;
            float4 v1 = *(const float4*)(sk + 4);
            float a = rr[p][0] * v0.x + rr[p][1] * v0.y + rr[p][2] * v0.z + rr[p][3] * v0.w
                    + rr[p][4] * v1.x + rr[p][5] * v1.y + rr[p][6] * v1.z;
            s_A[n * 65 + i] = a;
        }
        __syncthreads();

        // phase 3: C[n][o] += A_e[n][i] * W_e[i][o]   (FFMA2 over o-pairs)
        const float* wrow  = s_W + buf * (INTERM * EMB);
        const float* arow0 = s_A + nb * 65;
        const float* arow1 = s_A + (nb + 1) * 65;
        #pragma unroll 16
        for (int i = 0; i < INTERM; ++i) {
            ulonglong2 wA = *(const ulonglong2*)(wrow + i * EMB + ob);
            ulonglong2 wB = *(const ulonglong2*)(wrow + i * EMB + ob + 4);
            float af0 = arow0[i], af1 = arow1[i];
            ull a0 = pack2(af0, af0);
            ull a1 = pack2(af1, af1);
            c[0][0] = ffma2(a0, wA.x, c[0][0]);
            c[0][1] = ffma2(a0, wA.y, c[0][1]);
            c[0][2] = ffma2(a0, wB.x, c[0][2]);
            c[0][3] = ffma2(a0, wB.y, c[0][3]);
            c[1][0] = ffma2(a1, wA.x, c[1][0]);
            c[1][1] = ffma2(a1, wA.y, c[1][1]);
            c[1][2] = ffma2(a1, wB.x, c[1][2]);
            c[1][3] = ffma2(a1, wB.y, c[1][3]);
        }

        // commit prefetched weight slice to the other buffer
        if (e + 1 < EMB) {
            float4* ws = (float4*)(s_W + (buf ^ 1) * (INTERM * EMB));
            #pragma unroll
            for (int j = 0; j < 8; ++j) ws[tid + 256 * j] = wp[j];
        }
        __syncthreads();
        buf ^= 1;
    }

    // write C tile: thread owns edges (nb, nb+1), outputs [ob, ob+8)
    #pragma unroll
    for (int nn = 0; nn < 2; ++nn) {
        float o8[8];
        #pragma unroll
        for (int j = 0; j < 4; ++j) unpack2(c[nn][j], o8[2 * j], o8[2 * j + 1]);
        float4* dst = (float4*)(out + (size_t)(n0 + nb + nn) * NOUT + ob);
        dst[0] = make_float4(o8[0], o8[1], o8[2], o8[3]);
        dst[1] = make_float4(o8[4], o8[5], o8[6], o8[7]);
    }
}

extern "C" void kernel_launch(void* const* d_in, const int* in_sizes, int n_in,
                              void* d_out, int out_size) {
    // Remap float inputs by element count (insurance against ordering surprises).
    const float *rbf = 0, *sph = 0, *m = 0, *weight = 0;
    const void *idr = 0, *kix = 0;
    for (int i = 0; i < n_in; ++i) {
        long long sz = in_sizes[i];
        if      (sz == (long long)NE * INTERM * NSPH) rbf = (const float*)d_in[i];
        else if (sz == (long long)NE * NSPH * KMAX)   sph = (const float*)d_in[i];
        else if (sz == (long long)NTRIP * EMB)        m = (const float*)d_in[i];
        else if (sz == (long long)EMB * INTERM * NOUT) weight = (const float*)d_in[i];
        else if (sz == (long long)NTRIP) { if (!idr) idr = d_in[i]; else kix = d_in[i]; }
    }
    float* out = (float*)d_out;

    cudaFuncSetAttribute(fused_bilinear_kernel,
                         cudaFuncAttributeMaxDynamicSharedMemorySize, SMEM_BYTES);

    detect_kernel<<<1, 256>>>(idr, kix, NTRIP);
    build_idx_kernel<<<(NTRIP + 255) / 256, 256>>>(idr, kix, NTRIP);
    fused_bilinear_kernel<<<NE / MT, NTHREADS, SMEM_BYTES>>>(rbf, sph, m, weight, out);
}

// round 5
// speedup vs baseline: 2.3323x; 2.3313x over previous
#include <cuda_runtime.h>
#include <cstdint>

#define NE      20000
#define KMAX    16
#define NTRIP   (NE * KMAX)
#define EMB     128
#define INTERM  64
#define NSPH    7
#define NOUT    128
#define MT      128
#define NTHREADS 256
#define NTILES_M 157            // ceil(20000/128)
#define KSPLIT  2
#define CHUNKS  128             // chunks per CTA (half of 256 global)
#define PITCH   136             // smem row pitch in floats (conflict-free)

typedef unsigned long long ull;

// ---------------- persistent device scratch ----------------
__device__ int   d_trip[NTRIP];
__device__ int   d_is64;
__device__ float d_Wimg[256 * 4096];   // 4 MB tf32 image of weight, tiled [cg][k=32][n=128]

// ---------------- helpers ----------------
__device__ __forceinline__ ull pack2(float x, float y) {
    ull r; asm("mov.b64 %0, {%1,%2};" : "=l"(r) : "f"(x), "f"(y)); return r;
}
__device__ __forceinline__ void unpack2(ull v, float& x, float& y) {
    asm("mov.b64 {%0,%1}, %2;" : "=f"(x), "=f"(y) : "l"(v));
}
__device__ __forceinline__ ull ffma2(ull a, ull b, ull c) {
    ull d; asm("fma.rn.f32x2 %0, %1, %2, %3;" : "=l"(d) : "l"(a), "l"(b), "l"(c)); return d;
}
__device__ __forceinline__ ull mul2(ull a, ull b) {
    ull d; asm("mul.rn.f32x2 %0, %1, %2;" : "=l"(d) : "l"(a), "l"(b)); return d;
}
__device__ __forceinline__ uint32_t f2tf32(float f) {
    uint32_t v; asm("cvt.rna.tf32.f32 %0, %1;" : "=r"(v) : "f"(f)); return v;
}

#define MMA_TF32(d, a, b0, b1)                                                 \
    asm volatile("mma.sync.aligned.m16n8k8.row.col.f32.tf32.tf32.f32 "         \
        "{%0,%1,%2,%3}, {%4,%5,%6,%7}, {%8,%9}, {%0,%1,%2,%3};"                \
        : "+f"((d)[0]), "+f"((d)[1]), "+f"((d)[2]), "+f"((d)[3])               \
        : "r"((a)[0]), "r"((a)[1]), "r"((a)[2]), "r"((a)[3]),                  \
          "r"(b0), "r"(b1))

// ---------------- prologue kernels ----------------
__global__ void detect_kernel(const void* idr, const void* kix, int n) {
    __shared__ int bad;
    if (threadIdx.x == 0) bad = 0;
    __syncthreads();
    int cnt = n < 2048 ? n : 2048;
    const long long* a = (const long long*)idr;
    const long long* b = (const long long*)kix;
    for (int t = threadIdx.x; t < cnt; t += blockDim.x) {
        long long v = a[t], w = b[t];
        if (v < 0 || v >= NE || w < 0 || w >= KMAX) bad = 1;
    }
    __syncthreads();
    if (threadIdx.x == 0) d_is64 = bad ? 0 : 1;
}

__global__ void build_idx_kernel(const void* idr, const void* kix, int n) {
    int t = blockIdx.x * blockDim.x + threadIdx.x;
    if (t >= n) return;
    int e, k;
    if (d_is64) {
        e = (int)((const long long*)idr)[t];
        k = (int)((const long long*)kix)[t];
    } else {
        e = ((const int*)idr)[t];
        k = ((const int*)kix)[t];
    }
    if (e >= 0 && e < NE && k >= 0 && k < KMAX) d_trip[e * KMAX + k] = t;
}

__global__ void zero_out_kernel(float* out, int n) {
    int i = blockIdx.x * blockDim.x + threadIdx.x;
    if (i < n) out[i] = 0.f;
}

// tile cg = g*64+i holds B[k=e_in 0..31][n=o 0..127] = tf32(W[g*32+e_in][i][o])
__global__ void build_wimg_kernel(const float* __restrict__ W) {
    int tile = blockIdx.x;               // 0..255
    int g = tile >> 6, i = tile & 63;
    float* dst = d_Wimg + (size_t)tile * 4096;
    #pragma unroll
    for (int j = 0; j < 16; ++j) {
        int idx = threadIdx.x + 256 * j;
        int k = idx >> 7, o = idx & 127;
        float v = W[(size_t)(g * 32 + k) * (INTERM * NOUT) + i * NOUT + o];
        dst[idx] = __uint_as_float(f2tf32(v));
    }
}

// ---------------- main fused kernel ----------------
// smem float offsets
#define F_TRIP  0                          // 2048 ints
#define F_RB0   2048                       // 896 floats
#define F_RB1   2944
#define F_A0    3840                       // 32*136 = 4352 floats
#define F_A1    (F_A0 + 32 * PITCH)
#define F_B0    12544
#define F_B1    (F_B0 + 32 * PITCH)
#define SMEM_FLOATS (F_B1 + 32 * PITCH)    // 21248
#define SMEM_BYTES  (SMEM_FLOATS * 4)      // 84992

__global__ __launch_bounds__(NTHREADS, 1)
void fused_mma_kernel(const float* __restrict__ rbf,
                      const float* __restrict__ sph,
                      const float* __restrict__ m,
                      float* __restrict__ out) {
    extern __shared__ float sm[];
    int*   s_trip = (int*)sm;
    float* s_rb[2] = { sm + F_RB0, sm + F_RB1 };
    float* s_A[2]  = { sm + F_A0,  sm + F_A1  };
    float* s_B[2]  = { sm + F_B0,  sm + F_B1  };

    const int tid  = threadIdx.x;
    const int warp = tid >> 5, lane = tid & 31;
    const int mtile = blockIdx.x >> 1;
    const int kh    = blockIdx.x & 1;      // which K half
    const int n0    = mtile * MT;
    const int g0    = kh * 2;              // first e-group for this CTA

    // stage triplet ids (clamped)
    for (int x = tid; x < MT * KMAX; x += NTHREADS) {
        int edge = n0 + (x >> 4); if (edge >= NE) edge = NE - 1;
        int tr = d_trip[edge * KMAX + (x & 15)];
        s_trip[x] = (tr < 0) ? 0 : (tr >= NTRIP ? NTRIP - 1 : tr);
    }
    // stage rbf slice i=0 into rb[0]
    for (int x = tid; x < MT * NSPH; x += NTHREADS) {
        int e_ = x / 7, s_ = x - e_ * 7;
        int eg = n0 + e_; if (eg >= NE) eg = NE - 1;
        s_rb[0][x] = rbf[(size_t)eg * (INTERM * NSPH) + s_];
    }
    __syncthreads();

    // per-thread identity for A production: edge n (0..127), e-half h (0..1)
    const int n = tid & 127, h = tid >> 7;
    int nglob = n0 + n; if (nglob >= NE) nglob = NE - 1;

    ull sk[NSPH][8];   // sumk[s][e-pair] for this thread's 16 e's of current group

    auto phase1 = [&](int g) {
        #pragma unroll
        for (int s = 0; s < NSPH; ++s)
            #pragma unroll
            for (int ep = 0; ep < 8; ++ep) sk[s][ep] = 0ULL;
        const int ebase = g * 32 + h * 16;
        #pragma unroll
        for (int k = 0; k < KMAX; ++k) {
            const float4* mr = (const float4*)(m + (size_t)s_trip[n * KMAX + k] * EMB + ebase);
            float4 m0 = mr[0], m1 = mr[1], m2 = mr[2], m3 = mr[3];
            ull mp[8];
            mp[0] = pack2(m0.x, m0.y); mp[1] = pack2(m0.z, m0.w);
            mp[2] = pack2(m1.x, m1.y); mp[3] = pack2(m1.z, m1.w);
            mp[4] = pack2(m2.x, m2.y); mp[5] = pack2(m2.z, m2.w);
            mp[6] = pack2(m3.x, m3.y); mp[7] = pack2(m3.z, m3.w);
            const float* sp = sph + (size_t)nglob * (NSPH * KMAX) + k;
            #pragma unroll
            for (int s = 0; s < NSPH; ++s) {
                float sv = sp[s * KMAX];
                ull s2 = pack2(sv, sv);
                #pragma unroll
                for (int ep = 0; ep < 8; ++ep) sk[s][ep] = ffma2(s2, mp[ep], sk[s][ep]);
            }
        }
    };

    // prepare chunk cn: build A,B into buffer cn&1; stage rbf for i(cn+1)
    auto prepare = [&](int cn) {
        if (cn > 0 && (cn & 63) == 0) phase1(g0 + (cn >> 6));
        const int p = cn & 1;
        float* As = s_A[p];
        float* Bs = s_B[p];
        // phase 2: A[k][n] tf32, k = h*16 + (0..15)
        {
            const float* rb = s_rb[p] + n * NSPH;
            ull rr[NSPH];
            #pragma unroll
            for (int s = 0; s < NSPH; ++s) { float v = rb[s]; rr[s] = pack2(v, v); }
            #pragma unroll
            for (int ep = 0; ep < 8; ++ep) {
                ull acc = mul2(rr[0], sk[0][ep]);
                #pragma unroll
                for (int s = 1; s < NSPH; ++s) acc = ffma2(rr[s], sk[s][ep], acc);
                float f0, f1; unpack2(acc, f0, f1);
                int k = h * 16 + 2 * ep;
                As[k * PITCH + n]       = __uint_as_float(f2tf32(f0));
                As[(k + 1) * PITCH + n] = __uint_as_float(f2tf32(f1));
            }
        }
        // B tile copy (tf32 image, gmem->smem with pitch)
        {
            const int cg = kh * CHUNKS + cn;
            const float4* src = (const float4*)(d_Wimg + (size_t)cg * 4096);
            #pragma unroll
            for (int j = 0; j < 4; ++j) {
                int fidx = tid + 256 * j;
                int row = fidx >> 5, c4 = fidx & 31;
                *(float4*)(Bs + row * PITCH + c4 * 4) = src[fidx];
            }
        }
        // stage rbf for chunk cn+1 (slice i = (cn+1)&63) into rb[(cn+1)&1]
        {
            const int ni = (cn + 1) & 63;
            float* buf = s_rb[(cn + 1) & 1];
            for (int x = tid; x < MT * NSPH; x += NTHREADS) {
                int e_ = x / 7, s_ = x - e_ * 7;
                int eg = n0 + e_; if (eg >= NE) eg = NE - 1;
                buf[x] = rbf[(size_t)eg * (INTERM * NSPH) + ni * NSPH + s_];
            }
        }
    };

    phase1(g0);
    prepare(0);

    // ---- mma mainloop ----
    const int wm = (warp >> 2) * 64, wn = (warp & 3) * 32;
    const int q = lane >> 2, r = lane & 3;

    float acc[4][4][4];
    #pragma unroll
    for (int mi = 0; mi < 4; ++mi)
        #pragma unroll
        for (int ni = 0; ni < 4; ++ni)
            #pragma unroll
            for (int v = 0; v < 4; ++v) acc[mi][ni][v] = 0.f;

    for (int c = 0; c < CHUNKS; ++c) {
        __syncthreads();
        const uint32_t* Au = (const uint32_t*)s_A[c & 1];
        const uint32_t* Bu = (const uint32_t*)s_B[c & 1];
        #pragma unroll
        for (int ks = 0; ks < 4; ++ks) {
            const int kb = ks * 8;
            uint32_t a[4][4];
            #pragma unroll
            for (int mi = 0; mi < 4; ++mi) {
                int base = (kb + r) * PITCH + wm + mi * 16 + q;
                a[mi][0] = Au[base];
                a[mi][1] = Au[base + 8];
                a[mi][2] = Au[base + 4 * PITCH];
                a[mi][3] = Au[base + 4 * PITCH + 8];
            }
            #pragma unroll
            for (int ni = 0; ni < 4; ++ni) {
                uint32_t b0 = Bu[(kb + r) * PITCH + wn + ni * 8 + q];
                uint32_t b1 = Bu[(kb + r + 4) * PITCH + wn + ni * 8 + q];
                #pragma unroll
                for (int mi = 0; mi < 4; ++mi)
                    MMA_TF32(acc[mi][ni], a[mi], b0, b1);
            }
        }
        if (c < CHUNKS - 1) prepare(c + 1);
    }

    // ---- epilogue: atomic add partial (split-K) ----
    #pragma unroll
    for (int mi = 0; mi < 4; ++mi) {
        int row0 = n0 + wm + mi * 16 + q;
        int row1 = row0 + 8;
        #pragma unroll
        for (int ni = 0; ni < 4; ++ni) {
            int col = wn + ni * 8 + 2 * r;
            if (row0 < NE) {
                atomicAdd(&out[(size_t)row0 * NOUT + col],     acc[mi][ni][0]);
                atomicAdd(&out[(size_t)row0 * NOUT + col + 1], acc[mi][ni][1]);
            }
            if (row1 < NE) {
                atomicAdd(&out[(size_t)row1 * NOUT + col],     acc[mi][ni][2]);
                atomicAdd(&out[(size_t)row1 * NOUT + col + 1], acc[mi][ni][3]);
            }
        }
    }
}

extern "C" void kernel_launch(void* const* d_in, const int* in_sizes, int n_in,
                              void* d_out, int out_size) {
    const float *rbf = 0, *sph = 0, *m = 0, *weight = 0;
    const void *idr = 0, *kix = 0;
    for (int i = 0; i < n_in; ++i) {
        long long sz = in_sizes[i];
        if      (sz == (long long)NE * INTERM * NSPH)  rbf = (const float*)d_in[i];
        else if (sz == (long long)NE * NSPH * KMAX)    sph = (const float*)d_in[i];
        else if (sz == (long long)NTRIP * EMB)         m = (const float*)d_in[i];
        else if (sz == (long long)EMB * INTERM * NOUT) weight = (const float*)d_in[i];
        else if (sz == (long long)NTRIP) { if (!idr) idr = d_in[i]; else kix = d_in[i]; }
    }
    float* out = (float*)d_out;

    cudaFuncSetAttribute(fused_mma_kernel,
                         cudaFuncAttributeMaxDynamicSharedMemorySize, SMEM_BYTES);

    zero_out_kernel<<<(NE * NOUT + 255) / 256, 256>>>(out, NE * NOUT);
    detect_kernel<<<1, 256>>>(idr, kix, NTRIP);
    build_idx_kernel<<<(NTRIP + 255) / 256, 256>>>(idr, kix, NTRIP);
    build_wimg_kernel<<<256, 256>>>(weight);
    fused_mma_kernel<<<NTILES_M * KSPLIT, NTHREADS, SMEM_BYTES>>>(rbf, sph, m, out);
}